// round 14
// baseline (speedup 1.0000x reference)
#include <cuda_runtime.h>
#include <cuda_fp16.h>
#include <cstdint>

// ---------------- problem constants ----------------
#define S_LEN   2048
#define DMODEL  1024
#define DPH     64
#define BM      128
#define BN      128
#define NKT     16
#define NTHREADS 256

#define OUT_ELEMS (2048ULL * 2048ULL)            // B*S*D
#define DOT_ELEMS (32ULL * 2048ULL * 2048ULL)    // B*H*S*S

#define P_SCALE 0.00390625f                      // 2^-8: keep exp() inside fp16 range

// ---------------- smem layout (bytes) ----------------
#define STG0_OFF 0          // 32768: fp32 staging slot 0 (Q, even tiles); epilogue scratch
#define STG1_OFF 32768      // 32768: fp32 staging slot 1 (odd tiles)
#define KV0_OFF  65536      // 16384: KV fp16 buffer 0 (even tiles), swizzled
#define KV1_OFF  81920      // 16384: KV fp16 buffer 1 (odd tiles)
#define MW_OFF   98304      // 256  : mask bit-words
#define RS_OFF   98560      // 1024 : row-sum halves [2][128]
#define SMEM_BYTES 99584
#define OSTRIDE 68          // fp32 row stride of epilogue O scratch (bank-spread)

// ---------------- helpers ----------------
static __device__ __forceinline__ uint32_t smem_u32(const void* p) {
    uint32_t a;
    asm("{ .reg .u64 t; cvta.to.shared.u64 t, %1; cvt.u32.u64 %0, t; }" : "=r"(a) : "l"(p));
    return a;
}
static __device__ __forceinline__ uint32_t pack_f16x2(float lo, float hi) {
    __half2 p = __floats2half2_rn(lo, hi);       // .x = lo (low 16 bits)
    return *reinterpret_cast<uint32_t*>(&p);
}
static __device__ __forceinline__ void mma_f16(float* c, uint32_t a0, uint32_t a1,
                                               uint32_t a2, uint32_t a3,
                                               uint32_t b0, uint32_t b1) {
    asm volatile(
        "mma.sync.aligned.m16n8k16.row.col.f32.f16.f16.f32 "
        "{%0,%1,%2,%3}, {%4,%5,%6,%7}, {%8,%9}, {%0,%1,%2,%3};"
        : "+f"(c[0]), "+f"(c[1]), "+f"(c[2]), "+f"(c[3])
        : "r"(a0), "r"(a1), "r"(a2), "r"(a3), "r"(b0), "r"(b1));
}
static __device__ __forceinline__ void ldsm_x4(uint32_t& r0, uint32_t& r1,
                                               uint32_t& r2, uint32_t& r3, uint32_t addr) {
    asm volatile("ldmatrix.sync.aligned.m8n8.x4.shared.b16 {%0,%1,%2,%3}, [%4];"
                 : "=r"(r0), "=r"(r1), "=r"(r2), "=r"(r3) : "r"(addr));
}
static __device__ __forceinline__ void ldsm_x2t(uint32_t& r0, uint32_t& r1, uint32_t addr) {
    asm volatile("ldmatrix.sync.aligned.m8n8.x2.trans.shared.b16 {%0,%1}, [%2];"
                 : "=r"(r0), "=r"(r1) : "r"(addr));
}

// issue 32KB raw fp32 tile load: 128 rows x 64 floats, row stride DMODEL.
// THREAD-LOCAL staging: thread t loads exactly the float4s (idx = i*256+t)
// that it alone converts later -> no block sync needed between wait and convert.
static __device__ __forceinline__ void tile_load(uint32_t sdst, const float* g, int tid) {
#pragma unroll
    for (int i = 0; i < 8; ++i) {
        int idx = i * NTHREADS + tid;            // 0..2047 float4s
        int key = idx >> 4, c4 = idx & 15;
        uint32_t sa = sdst + (uint32_t)idx * 16;
        const float* ga = g + (size_t)key * DMODEL + c4 * 4;
        asm volatile("cp.async.cg.shared.global [%0], [%1], 16;" :: "r"(sa), "l"(ga));
    }
    asm volatile("cp.async.commit_group;");
}
#define CP_WAIT0() asm volatile("cp.async.wait_group 0;" ::: "memory")
#define CP_WAIT1() asm volatile("cp.async.wait_group 1;" ::: "memory")

// convert own staged fp32 tile chunk -> fp16 KV buffer (swizzled)
static __device__ __forceinline__ void convert_tile(char* smem, const float* stg,
                                                    uint32_t kv_off, int tid) {
#pragma unroll
    for (int i = 0; i < 8; ++i) {
        int idx = i * NTHREADS + tid;
        int key = idx >> 4, c4 = idx & 15;
        float4 v = *reinterpret_cast<const float4*>(stg + idx * 4);
        uint32_t voff = kv_off + (uint32_t)key * 128 +
                        (((uint32_t)(c4 * 8)) ^ ((uint32_t)(key & 7) << 4));
        *reinterpret_cast<uint2*>(smem + voff) =
            make_uint2(pack_f16x2(v.x, v.y), pack_f16x2(v.z, v.w));
    }
}

// ---------------- fused MHA: 32x64 warp tiles, double-buffered KV, 1 sync/tile ----
__global__ void __launch_bounds__(NTHREADS, 1)
mha_kernel(const float* __restrict__ X, const int* __restrict__ mask,
           float* __restrict__ out, float* __restrict__ dp) {
    extern __shared__ char smem[];
    const uint32_t sbase = smem_u32(smem);
    float* stgf = reinterpret_cast<float*>(smem + STG0_OFF);
    uint32_t* mask_words = reinterpret_cast<uint32_t*>(smem + MW_OFF);
    float* rsh = reinterpret_cast<float*>(smem + RS_OFF);   // [2][128]

    const int tid  = threadIdx.x;
    const int wid  = tid >> 5;
    const int lane = tid & 31;
    const int qq   = lane & 3;           // quad lane
    const int lr4  = lane >> 2;          // 0..7
    const int wk   = wid >> 2;           // key-half 0/1
    const int WKEY = wk * 64;            // key base within tile
    const int WROW = (wid & 3) * 32;     // q-row base

    const int qt = blockIdx.x;
    const int bh = blockIdx.y;
    const int b  = bh >> 4;
    const int h  = bh & 15;

    // ldmatrix addressing for S-GEMM B (K rows = keys, non-trans, x4)
    const int krow = lane & 7;
    const int kg1  = (lane >> 3) & 1;    // +8 in k (feature)
    const int kg2  = (lane >> 4) & 1;    // +8 in n (key)
    const uint32_t kxor  = (uint32_t)(krow << 4);
    const uint32_t kbase = sbase + KV0_OFF + (uint32_t)((WKEY + kg2 * 8 + krow) * 128);
    const uint32_t kcol0 = (uint32_t)(kg1 * 16);
    // ldmatrix addressing for PV B (V rows = keys, trans, x2)
    const int i2 = lane & 15;
    const uint32_t vxor  = (uint32_t)((i2 & 7) << 4);
    const uint32_t vbase = sbase + KV0_OFF + (uint32_t)((WKEY + i2) * 128);

    // mask bitset: 64 words cover 2048 keys
    for (int j = wid; j < S_LEN / 32; j += 8) {
        int m = mask[b * S_LEN + j * 32 + lane];
        unsigned wv = __ballot_sync(0xFFFFFFFFu, m != 0);
        if (lane == 0) mask_words[j] = wv;
    }

    // ---- prologue: Q tile -> qa fragments ----
    const float* Xbh = X + (size_t)b * S_LEN * DMODEL + (size_t)h * DPH;
    tile_load(sbase + STG0_OFF, Xbh + (size_t)(qt * BM) * DMODEL, tid);
    CP_WAIT0();
    __syncthreads();

    uint32_t qa[2][4][4];
#pragma unroll
    for (int rb = 0; rb < 2; ++rb) {
        int r0 = WROW + rb * 16 + lr4;
#pragma unroll
        for (int ks = 0; ks < 4; ++ks) {
            int k0 = ks * 16 + 2 * qq;
            qa[rb][ks][0] = pack_f16x2(stgf[r0 * 64 + k0],           stgf[r0 * 64 + k0 + 1]);
            qa[rb][ks][1] = pack_f16x2(stgf[(r0 + 8) * 64 + k0],     stgf[(r0 + 8) * 64 + k0 + 1]);
            qa[rb][ks][2] = pack_f16x2(stgf[r0 * 64 + k0 + 8],       stgf[r0 * 64 + k0 + 9]);
            qa[rb][ks][3] = pack_f16x2(stgf[(r0 + 8) * 64 + k0 + 8], stgf[(r0 + 8) * 64 + k0 + 9]);
        }
    }
    __syncthreads();

    // ---- pipeline fill: tiles 0 and 1 in flight; convert tile 0 ----
    tile_load(sbase + STG0_OFF, Xbh, tid);
    tile_load(sbase + STG1_OFF, Xbh + (size_t)BN * DMODEL, tid);
    CP_WAIT1();                                   // own tile-0 chunks landed
    convert_tile(smem, stgf, (uint32_t)KV0_OFF, tid);   // thread-local read

    float oa[2][8][4];
#pragma unroll
    for (int rb = 0; rb < 2; ++rb)
#pragma unroll
        for (int nb = 0; nb < 8; ++nb)
#pragma unroll
            for (int j = 0; j < 4; ++j) oa[rb][nb][j] = 0.0f;
    float rs[2][2] = {{0.0f, 0.0f}, {0.0f, 0.0f}};

    const int qrow0 = qt * BM + WROW + lr4;
    float* dpr = dp ? dp + ((size_t)bh * S_LEN + qrow0) * S_LEN + WKEY + 2 * qq : (float*)0;

#pragma unroll 1
    for (int kt = 0; kt < NKT; ++kt) {
        // ONE sync per tile: guarantees (a) KV[kt&1] fully converted by all
        // threads, (b) previous tile's compute done reading KV[(kt+1)&1],
        // (c) previous convert done reading stg[kt&1].
        __syncthreads();

        if (kt + 2 < NKT)
            tile_load(sbase + ((kt & 1) ? STG1_OFF : STG0_OFF),
                      Xbh + (size_t)((kt + 2) * BN) * DMODEL, tid);
        if (kt + 1 < NKT) {
            if (kt + 2 < NKT) { CP_WAIT1(); } else { CP_WAIT0(); }
            convert_tile(smem,
                         reinterpret_cast<const float*>(smem + (((kt + 1) & 1) ? STG1_OFF : STG0_OFF)),
                         (uint32_t)(((kt + 1) & 1) ? KV1_OFF : KV0_OFF), tid);
        }

        const uint32_t kvo = (uint32_t)((kt & 1) << 14);     // +16384 for odd tiles

        // ---- S = Q K^T (fp16 m16n8k16): 2 row-blocks share each B fragment ----
        float sa[2][8][4];
#pragma unroll
        for (int rb = 0; rb < 2; ++rb)
#pragma unroll
            for (int nb = 0; nb < 8; ++nb)
#pragma unroll
                for (int j = 0; j < 4; ++j) sa[rb][nb][j] = 0.0f;

#pragma unroll
        for (int ks = 0; ks < 4; ++ks) {
            uint32_t kss = (uint32_t)(ks * 32) + kcol0;
#pragma unroll
            for (int nb4 = 0; nb4 < 4; ++nb4) {              // 16 keys per iter
                uint32_t b0, b1, b2, b3;
                ldsm_x4(b0, b1, b2, b3, kbase + kvo + (uint32_t)(nb4 * 2048) + (kss ^ kxor));
#pragma unroll
                for (int rb = 0; rb < 2; ++rb) {
                    mma_f16(sa[rb][2 * nb4],     qa[rb][ks][0], qa[rb][ks][1],
                            qa[rb][ks][2], qa[rb][ks][3], b0, b1);
                    mma_f16(sa[rb][2 * nb4 + 1], qa[rb][ks][0], qa[rb][ks][1],
                            qa[rb][ks][2], qa[rb][ks][3], b2, b3);
                }
            }
        }

        // ---- scale, mask, write dot_prod, exp, pack P ----
        uint32_t mwA = mask_words[kt * 4 + wk * 2];
        uint32_t mwB = mask_words[kt * 4 + wk * 2 + 1];
        bool tile_all = ((mwA & mwB) == 0xFFFFFFFFu);

        uint32_t ph0[2][8], ph1[2][8];
#pragma unroll
        for (int rb = 0; rb < 2; ++rb) {
            float* dpr0 = dpr ? dpr + (size_t)(rb * 16) * S_LEN : (float*)0;
            float* dpr1 = dpr0 ? dpr0 + 8 * (size_t)S_LEN : (float*)0;
#pragma unroll
            for (int nb = 0; nb < 8; ++nb) {
                float c0 = sa[rb][nb][0] * 0.125f, c1 = sa[rb][nb][1] * 0.125f;
                float c2 = sa[rb][nb][2] * 0.125f, c3 = sa[rb][nb][3] * 0.125f;
                if (!tile_all) {
                    int col = nb * 8 + 2 * qq;
                    uint32_t w = (nb < 4) ? mwA : mwB;
                    if (!((w >> (col & 31)) & 1u)) { c0 = -1e20f; c2 = -1e20f; }
                    if (!((w >> ((col + 1) & 31)) & 1u)) { c1 = -1e20f; c3 = -1e20f; }
                }
                if (dpr0) {
                    int coff = kt * BN + nb * 8;
                    *reinterpret_cast<float2*>(dpr0 + coff) = make_float2(c0, c1);
                    *reinterpret_cast<float2*>(dpr1 + coff) = make_float2(c2, c3);
                }
                float p0 = __expf(c0) * P_SCALE, p1 = __expf(c1) * P_SCALE;
                float p2 = __expf(c2) * P_SCALE, p3 = __expf(c3) * P_SCALE;
                rs[rb][0] += p0 + p1;
                rs[rb][1] += p2 + p3;
                ph0[rb][nb] = pack_f16x2(p0, p1);
                ph1[rb][nb] = pack_f16x2(p2, p3);
            }
        }

        // ---- O += P V: both row-blocks share each V fragment ----
#pragma unroll
        for (int kg = 0; kg < 4; ++kg) {
#pragma unroll
            for (int nb = 0; nb < 8; ++nb) {
                uint32_t b0, b1;
                ldsm_x2t(b0, b1, vbase + kvo + (uint32_t)kg * 2048 + (((uint32_t)(nb * 16)) ^ vxor));
#pragma unroll
                for (int rb = 0; rb < 2; ++rb)
                    mma_f16(oa[rb][nb], ph0[rb][2 * kg], ph1[rb][2 * kg],
                            ph0[rb][2 * kg + 1], ph1[rb][2 * kg + 1], b0, b1);
            }
        }
    }

    // ---- epilogue: quad-reduce row sums, cross-half combine, O reduce ----
#pragma unroll
    for (int rb = 0; rb < 2; ++rb) {
#pragma unroll
        for (int s = 1; s <= 2; s <<= 1) {
            rs[rb][0] += __shfl_xor_sync(0xFFFFFFFFu, rs[rb][0], s);
            rs[rb][1] += __shfl_xor_sync(0xFFFFFFFFu, rs[rb][1], s);
        }
    }
    __syncthreads();    // all compute done; no cp.async pending; staging free

    float* osum = stgf;   // OSTRIDE-stride 128x64 fp32 scratch (in STG0/STG1 area)
    if (wk == 1) {
#pragma unroll
        for (int rb = 0; rb < 2; ++rb) {
            int r0 = WROW + rb * 16 + lr4;
            if (qq == 0) { rsh[128 + r0] = rs[rb][0]; rsh[128 + r0 + 8] = rs[rb][1]; }
#pragma unroll
            for (int nb = 0; nb < 8; ++nb) {
                int col = nb * 8 + 2 * qq;
                *reinterpret_cast<float2*>(osum + r0 * OSTRIDE + col) =
                    make_float2(oa[rb][nb][0], oa[rb][nb][1]);
                *reinterpret_cast<float2*>(osum + (r0 + 8) * OSTRIDE + col) =
                    make_float2(oa[rb][nb][2], oa[rb][nb][3]);
            }
        }
    } else {
#pragma unroll
        for (int rb = 0; rb < 2; ++rb) {
            int r0 = WROW + rb * 16 + lr4;
            if (qq == 0) { rsh[r0] = rs[rb][0]; rsh[r0 + 8] = rs[rb][1]; }
        }
    }
    __syncthreads();

    if (wk == 0 && out) {
#pragma unroll
        for (int rb = 0; rb < 2; ++rb) {
            int r0 = WROW + rb * 16 + lr4;
            float inv0 = 1.0f / (rsh[r0] + rsh[128 + r0]);
            float inv1 = 1.0f / (rsh[r0 + 8] + rsh[128 + r0 + 8]);
            float* or0 = out + ((size_t)(b * S_LEN + qt * BM + r0)) * DMODEL + h * DPH + 2 * qq;
            float* or1 = or0 + 8 * (size_t)DMODEL;
#pragma unroll
            for (int nb = 0; nb < 8; ++nb) {
                int col = nb * 8 + 2 * qq;
                float2 s0 = *reinterpret_cast<float2*>(osum + r0 * OSTRIDE + col);
                float2 s1 = *reinterpret_cast<float2*>(osum + (r0 + 8) * OSTRIDE + col);
                *reinterpret_cast<float2*>(or0 + nb * 8) =
                    make_float2((oa[rb][nb][0] + s0.x) * inv0, (oa[rb][nb][1] + s0.y) * inv0);
                *reinterpret_cast<float2*>(or1 + nb * 8) =
                    make_float2((oa[rb][nb][2] + s1.x) * inv1, (oa[rb][nb][3] + s1.y) * inv1);
            }
        }
    }
}

// ---------------- launch ----------------
extern "C" void kernel_launch(void* const* d_in, const int* in_sizes, int n_in,
                              void* d_out, int out_size) {
    const float* X  = (const float*)d_in[0];
    const int* mask = (const int*)d_in[1];

    float* out = (float*)0;
    float* dp  = (float*)0;
    size_t os = (size_t)out_size;
    if (os >= OUT_ELEMS + DOT_ELEMS) {
        out = (float*)d_out;
        dp  = (float*)d_out + OUT_ELEMS;
    } else if (os == DOT_ELEMS) {
        dp = (float*)d_out;
    } else {
        out = (float*)d_out;
    }

    cudaFuncSetAttribute(mha_kernel, cudaFuncAttributeMaxDynamicSharedMemorySize, SMEM_BYTES);
    dim3 grid(S_LEN / BM, 32);
    mha_kernel<<<grid, NTHREADS, SMEM_BYTES>>>(X, mask, out, dp);
}

// round 15
// speedup vs baseline: 1.1388x; 1.1388x over previous
#include <cuda_runtime.h>
#include <cuda_fp16.h>
#include <cstdint>

// ---------------- problem constants ----------------
#define S_LEN   2048
#define DMODEL  1024
#define DPH     64
#define BM      128
#define BN      128
#define NKT     16
#define NTHREADS 256

#define OUT_ELEMS (2048ULL * 2048ULL)            // B*S*D
#define DOT_ELEMS (32ULL * 2048ULL * 2048ULL)    // B*H*S*S

#define LOG2E 1.4426950408889634f
#define P_BIAS 8.0f                              // p = 2^(c*log2e - 8): fp16-safe range
#define P_SCALE 0.00390625f                      // 2^-8 (rowsum uses same scaled p)

// ---------------- smem layout (bytes) ----------------
#define STG0_OFF 0          // 32768: fp32 staging slot 0 (Q, even tiles); epilogue scratch
#define STG1_OFF 32768      // 32768: fp32 staging slot 1 (odd tiles)
#define KV0_OFF  65536      // 16384: KV fp16 buffer 0 (even tiles), swizzled
#define KV1_OFF  81920      // 16384: KV fp16 buffer 1 (odd tiles)
#define MW_OFF   98304      // 256  : mask bit-words
#define RS_OFF   98560      // 1024 : row-sum halves [2][128]
#define SMEM_BYTES 99584
#define OSTRIDE 68          // fp32 row stride of epilogue O scratch (bank-spread)

// ---------------- helpers ----------------
static __device__ __forceinline__ uint32_t smem_u32(const void* p) {
    uint32_t a;
    asm("{ .reg .u64 t; cvta.to.shared.u64 t, %1; cvt.u32.u64 %0, t; }" : "=r"(a) : "l"(p));
    return a;
}
static __device__ __forceinline__ uint32_t pack_f16x2(float lo, float hi) {
    __half2 p = __floats2half2_rn(lo, hi);       // .x = lo (low 16 bits)
    return *reinterpret_cast<uint32_t*>(&p);
}
static __device__ __forceinline__ float ex2_approx(float x) {
    float r;
    asm("ex2.approx.f32 %0, %1;" : "=f"(r) : "f"(x));
    return r;
}
static __device__ __forceinline__ void mma_f16(float* c, uint32_t a0, uint32_t a1,
                                               uint32_t a2, uint32_t a3,
                                               uint32_t b0, uint32_t b1) {
    asm volatile(
        "mma.sync.aligned.m16n8k16.row.col.f32.f16.f16.f32 "
        "{%0,%1,%2,%3}, {%4,%5,%6,%7}, {%8,%9}, {%0,%1,%2,%3};"
        : "+f"(c[0]), "+f"(c[1]), "+f"(c[2]), "+f"(c[3])
        : "r"(a0), "r"(a1), "r"(a2), "r"(a3), "r"(b0), "r"(b1));
}
static __device__ __forceinline__ void ldsm_x4(uint32_t& r0, uint32_t& r1,
                                               uint32_t& r2, uint32_t& r3, uint32_t addr) {
    asm volatile("ldmatrix.sync.aligned.m8n8.x4.shared.b16 {%0,%1,%2,%3}, [%4];"
                 : "=r"(r0), "=r"(r1), "=r"(r2), "=r"(r3) : "r"(addr));
}
static __device__ __forceinline__ void ldsm_x2t(uint32_t& r0, uint32_t& r1, uint32_t addr) {
    asm volatile("ldmatrix.sync.aligned.m8n8.x2.trans.shared.b16 {%0,%1}, [%2];"
                 : "=r"(r0), "=r"(r1) : "r"(addr));
}

// issue 32KB raw fp32 tile load (thread-local staging; no sync needed pre-convert)
static __device__ __forceinline__ void tile_load(uint32_t sdst, const float* g, int tid) {
#pragma unroll
    for (int i = 0; i < 8; ++i) {
        int idx = i * NTHREADS + tid;            // 0..2047 float4s
        int key = idx >> 4, c4 = idx & 15;
        uint32_t sa = sdst + (uint32_t)idx * 16;
        const float* ga = g + (size_t)key * DMODEL + c4 * 4;
        asm volatile("cp.async.cg.shared.global [%0], [%1], 16;" :: "r"(sa), "l"(ga));
    }
    asm volatile("cp.async.commit_group;");
}
#define CP_WAIT0() asm volatile("cp.async.wait_group 0;" ::: "memory")
#define CP_WAIT1() asm volatile("cp.async.wait_group 1;" ::: "memory")

// convert own staged fp32 tile chunk -> fp16 KV buffer (swizzled)
static __device__ __forceinline__ void convert_tile(char* smem, const float* stg,
                                                    uint32_t kv_off, int tid) {
#pragma unroll
    for (int i = 0; i < 8; ++i) {
        int idx = i * NTHREADS + tid;
        int key = idx >> 4, c4 = idx & 15;
        float4 v = *reinterpret_cast<const float4*>(stg + idx * 4);
        uint32_t voff = kv_off + (uint32_t)key * 128 +
                        (((uint32_t)(c4 * 8)) ^ ((uint32_t)(key & 7) << 4));
        *reinterpret_cast<uint2*>(smem + voff) =
            make_uint2(pack_f16x2(v.x, v.y), pack_f16x2(v.z, v.w));
    }
}

// ---------------- fused MHA: chunk-interleaved S/exp/PV, double-buffered KV ----
__global__ void __launch_bounds__(NTHREADS, 1)
mha_kernel(const float* __restrict__ X, const int* __restrict__ mask,
           float* __restrict__ out, float* __restrict__ dp) {
    extern __shared__ char smem[];
    const uint32_t sbase = smem_u32(smem);
    float* stgf = reinterpret_cast<float*>(smem + STG0_OFF);
    uint32_t* mask_words = reinterpret_cast<uint32_t*>(smem + MW_OFF);
    float* rsh = reinterpret_cast<float*>(smem + RS_OFF);   // [2][128]

    const int tid  = threadIdx.x;
    const int wid  = tid >> 5;
    const int lane = tid & 31;
    const int qq   = lane & 3;           // quad lane
    const int lr4  = lane >> 2;          // 0..7
    const int wk   = wid >> 2;           // key-half 0/1
    const int WKEY = wk * 64;            // key base within tile
    const int WROW = (wid & 3) * 32;     // q-row base

    const int qt = blockIdx.x;
    const int bh = blockIdx.y;
    const int b  = bh >> 4;
    const int h  = bh & 15;

    // ldmatrix addressing (S-GEMM B: keys, non-trans x4; PV B: trans x2)
    const int krow = lane & 7;
    const int kg1  = (lane >> 3) & 1;
    const int kg2  = (lane >> 4) & 1;
    const uint32_t kxor  = (uint32_t)(krow << 4);
    const uint32_t kbase = sbase + KV0_OFF + (uint32_t)((WKEY + kg2 * 8 + krow) * 128);
    const uint32_t kcol0 = (uint32_t)(kg1 * 16);
    const int i2 = lane & 15;
    const uint32_t vxor  = (uint32_t)((i2 & 7) << 4);
    const uint32_t vbase = sbase + KV0_OFF + (uint32_t)((WKEY + i2) * 128);

    // mask bitset: 64 words cover 2048 keys
    for (int j = wid; j < S_LEN / 32; j += 8) {
        int m = mask[b * S_LEN + j * 32 + lane];
        unsigned wv = __ballot_sync(0xFFFFFFFFu, m != 0);
        if (lane == 0) mask_words[j] = wv;
    }

    // ---- prologue: Q tile -> qa fragments, PRE-SCALED by 1/8 ----
    const float* Xbh = X + (size_t)b * S_LEN * DMODEL + (size_t)h * DPH;
    tile_load(sbase + STG0_OFF, Xbh + (size_t)(qt * BM) * DMODEL, tid);
    CP_WAIT0();
    __syncthreads();

    uint32_t qa[2][4][4];
#pragma unroll
    for (int rb = 0; rb < 2; ++rb) {
        int r0 = WROW + rb * 16 + lr4;
#pragma unroll
        for (int ks = 0; ks < 4; ++ks) {
            int k0 = ks * 16 + 2 * qq;
            qa[rb][ks][0] = pack_f16x2(stgf[r0 * 64 + k0] * 0.125f,
                                       stgf[r0 * 64 + k0 + 1] * 0.125f);
            qa[rb][ks][1] = pack_f16x2(stgf[(r0 + 8) * 64 + k0] * 0.125f,
                                       stgf[(r0 + 8) * 64 + k0 + 1] * 0.125f);
            qa[rb][ks][2] = pack_f16x2(stgf[r0 * 64 + k0 + 8] * 0.125f,
                                       stgf[r0 * 64 + k0 + 9] * 0.125f);
            qa[rb][ks][3] = pack_f16x2(stgf[(r0 + 8) * 64 + k0 + 8] * 0.125f,
                                       stgf[(r0 + 8) * 64 + k0 + 9] * 0.125f);
        }
    }
    __syncthreads();

    // ---- pipeline fill: tiles 0 and 1 in flight; convert tile 0 ----
    tile_load(sbase + STG0_OFF, Xbh, tid);
    tile_load(sbase + STG1_OFF, Xbh + (size_t)BN * DMODEL, tid);
    CP_WAIT1();
    convert_tile(smem, stgf, (uint32_t)KV0_OFF, tid);

    float oa[2][8][4];
#pragma unroll
    for (int rb = 0; rb < 2; ++rb)
#pragma unroll
        for (int nb = 0; nb < 8; ++nb)
#pragma unroll
            for (int j = 0; j < 4; ++j) oa[rb][nb][j] = 0.0f;
    float rs[2][2] = {{0.0f, 0.0f}, {0.0f, 0.0f}};

    const int qrow0 = qt * BM + WROW + lr4;
    float* dpr = dp ? dp + ((size_t)bh * S_LEN + qrow0) * S_LEN + WKEY + 2 * qq : (float*)0;

#pragma unroll 1
    for (int kt = 0; kt < NKT; ++kt) {
        __syncthreads();   // KV[kt&1] converted; prior compute/convert done

        if (kt + 2 < NKT)
            tile_load(sbase + ((kt & 1) ? STG1_OFF : STG0_OFF),
                      Xbh + (size_t)((kt + 2) * BN) * DMODEL, tid);
        if (kt + 1 < NKT) {
            if (kt + 2 < NKT) { CP_WAIT1(); } else { CP_WAIT0(); }
            convert_tile(smem,
                         reinterpret_cast<const float*>(smem + (((kt + 1) & 1) ? STG1_OFF : STG0_OFF)),
                         (uint32_t)(((kt + 1) & 1) ? KV1_OFF : KV0_OFF), tid);
        }

        const uint32_t kvo = (uint32_t)((kt & 1) << 14);

        uint32_t mwA = mask_words[kt * 4 + wk * 2];
        uint32_t mwB = mask_words[kt * 4 + wk * 2 + 1];
        bool tile_all = ((mwA & mwB) == 0xFFFFFFFFu);

        float* dprA = dpr ? dpr + kt * BN : (float*)0;

        // ---- 4 x 16-key chunks: S-MMA -> mask/dp -> exp -> pack -> PV-MMA ----
#pragma unroll
        for (int kg = 0; kg < 4; ++kg) {
            // S chunk: 16 keys, all 4 feature steps
            float sc[2][2][4];
#pragma unroll
            for (int rb = 0; rb < 2; ++rb)
#pragma unroll
                for (int np = 0; np < 2; ++np)
#pragma unroll
                    for (int j = 0; j < 4; ++j) sc[rb][np][j] = 0.0f;

#pragma unroll
            for (int ks = 0; ks < 4; ++ks) {
                uint32_t kss = (uint32_t)(ks * 32) + kcol0;
                uint32_t b0, b1, b2, b3;
                ldsm_x4(b0, b1, b2, b3, kbase + kvo + (uint32_t)(kg * 2048) + (kss ^ kxor));
#pragma unroll
                for (int rb = 0; rb < 2; ++rb) {
                    mma_f16(sc[rb][0], qa[rb][ks][0], qa[rb][ks][1],
                            qa[rb][ks][2], qa[rb][ks][3], b0, b1);
                    mma_f16(sc[rb][1], qa[rb][ks][0], qa[rb][ks][1],
                            qa[rb][ks][2], qa[rb][ks][3], b2, b3);
                }
            }

            // mask, dp store, exp (fused 2^(c*log2e - 8)), pack
            uint32_t pk0[2][2], pk1[2][2];
#pragma unroll
            for (int rb = 0; rb < 2; ++rb) {
                float* dpr0 = dprA ? dprA + (size_t)(rb * 16) * S_LEN : (float*)0;
                float* dpr1 = dpr0 ? dpr0 + 8 * (size_t)S_LEN : (float*)0;
#pragma unroll
                for (int np = 0; np < 2; ++np) {
                    int nb = 2 * kg + np;
                    float c0 = sc[rb][np][0], c1 = sc[rb][np][1];
                    float c2 = sc[rb][np][2], c3 = sc[rb][np][3];
                    if (!tile_all) {
                        int col = nb * 8 + 2 * qq;
                        uint32_t w = (nb < 4) ? mwA : mwB;
                        if (!((w >> (col & 31)) & 1u)) { c0 = -1e20f; c2 = -1e20f; }
                        if (!((w >> ((col + 1) & 31)) & 1u)) { c1 = -1e20f; c3 = -1e20f; }
                    }
                    if (dpr0) {
                        int coff = nb * 8;
                        *reinterpret_cast<float2*>(dpr0 + coff) = make_float2(c0, c1);
                        *reinterpret_cast<float2*>(dpr1 + coff) = make_float2(c2, c3);
                    }
                    float p0 = ex2_approx(fmaf(c0, LOG2E, -P_BIAS));
                    float p1 = ex2_approx(fmaf(c1, LOG2E, -P_BIAS));
                    float p2 = ex2_approx(fmaf(c2, LOG2E, -P_BIAS));
                    float p3 = ex2_approx(fmaf(c3, LOG2E, -P_BIAS));
                    rs[rb][0] += p0 + p1;
                    rs[rb][1] += p2 + p3;
                    pk0[rb][np] = pack_f16x2(p0, p1);
                    pk1[rb][np] = pack_f16x2(p2, p3);
                }
            }

            // PV chunk: these 16 keys into O
#pragma unroll
            for (int nb = 0; nb < 8; ++nb) {
                uint32_t b0, b1;
                ldsm_x2t(b0, b1, vbase + kvo + (uint32_t)(kg * 2048) + (((uint32_t)(nb * 16)) ^ vxor));
#pragma unroll
                for (int rb = 0; rb < 2; ++rb)
                    mma_f16(oa[rb][nb], pk0[rb][0], pk1[rb][0], pk0[rb][1], pk1[rb][1], b0, b1);
            }
        }
    }

    // ---- epilogue: quad-reduce row sums, cross-half combine, O reduce ----
#pragma unroll
    for (int rb = 0; rb < 2; ++rb) {
#pragma unroll
        for (int s = 1; s <= 2; s <<= 1) {
            rs[rb][0] += __shfl_xor_sync(0xFFFFFFFFu, rs[rb][0], s);
            rs[rb][1] += __shfl_xor_sync(0xFFFFFFFFu, rs[rb][1], s);
        }
    }
    __syncthreads();    // all compute done; no cp.async pending; staging free

    float* osum = stgf;   // OSTRIDE-stride 128x64 fp32 scratch
    if (wk == 1) {
#pragma unroll
        for (int rb = 0; rb < 2; ++rb) {
            int r0 = WROW + rb * 16 + lr4;
            if (qq == 0) { rsh[128 + r0] = rs[rb][0]; rsh[128 + r0 + 8] = rs[rb][1]; }
#pragma unroll
            for (int nb = 0; nb < 8; ++nb) {
                int col = nb * 8 + 2 * qq;
                *reinterpret_cast<float2*>(osum + r0 * OSTRIDE + col) =
                    make_float2(oa[rb][nb][0], oa[rb][nb][1]);
                *reinterpret_cast<float2*>(osum + (r0 + 8) * OSTRIDE + col) =
                    make_float2(oa[rb][nb][2], oa[rb][nb][3]);
            }
        }
    } else {
#pragma unroll
        for (int rb = 0; rb < 2; ++rb) {
            int r0 = WROW + rb * 16 + lr4;
            if (qq == 0) { rsh[r0] = rs[rb][0]; rsh[r0 + 8] = rs[rb][1]; }
        }
    }
    __syncthreads();

    if (wk == 0 && out) {
#pragma unroll
        for (int rb = 0; rb < 2; ++rb) {
            int r0 = WROW + rb * 16 + lr4;
            float inv0 = 1.0f / (rsh[r0] + rsh[128 + r0]);
            float inv1 = 1.0f / (rsh[r0 + 8] + rsh[128 + r0 + 8]);
            float* or0 = out + ((size_t)(b * S_LEN + qt * BM + r0)) * DMODEL + h * DPH + 2 * qq;
            float* or1 = or0 + 8 * (size_t)DMODEL;
#pragma unroll
            for (int nb = 0; nb < 8; ++nb) {
                int col = nb * 8 + 2 * qq;
                float2 s0 = *reinterpret_cast<float2*>(osum + r0 * OSTRIDE + col);
                float2 s1 = *reinterpret_cast<float2*>(osum + (r0 + 8) * OSTRIDE + col);
                *reinterpret_cast<float2*>(or0 + nb * 8) =
                    make_float2((oa[rb][nb][0] + s0.x) * inv0, (oa[rb][nb][1] + s0.y) * inv0);
                *reinterpret_cast<float2*>(or1 + nb * 8) =
                    make_float2((oa[rb][nb][2] + s1.x) * inv1, (oa[rb][nb][3] + s1.y) * inv1);
            }
        }
    }
}

// ---------------- launch ----------------
extern "C" void kernel_launch(void* const* d_in, const int* in_sizes, int n_in,
                              void* d_out, int out_size) {
    const float* X  = (const float*)d_in[0];
    const int* mask = (const int*)d_in[1];

    float* out = (float*)0;
    float* dp  = (float*)0;
    size_t os = (size_t)out_size;
    if (os >= OUT_ELEMS + DOT_ELEMS) {
        out = (float*)d_out;
        dp  = (float*)d_out + OUT_ELEMS;
    } else if (os == DOT_ELEMS) {
        dp = (float*)d_out;
    } else {
        out = (float*)d_out;
    }

    cudaFuncSetAttribute(mha_kernel, cudaFuncAttributeMaxDynamicSharedMemorySize, SMEM_BYTES);
    dim3 grid(S_LEN / BM, 32);
    mha_kernel<<<grid, NTHREADS, SMEM_BYTES>>>(X, mask, out, dp);
}